// round 5
// baseline (speedup 1.0000x reference)
#include <cuda_runtime.h>
#include <cuda_fp16.h>
#include <cstdint>
#include <math.h>

// Problem constants
#define B_    4
#define S_    4096
#define H_    2048
#define DFF_  8192
#define NTOK  (B_*S_)      // 16384 tokens
#define KCAP  (S_/2)       // top-k k = 2048
#define EPSF  1e-5f

// ---------------- static device scratch (allocation-free rule) ----------------
__device__ float  g_weights[NTOK];
__device__ float  g_rstd1[NTOK];
__device__ float  g_thresh[B_];
__device__ int    g_selidx[NTOK];
__device__ int    g_count;

__device__ __half g_bufA[(size_t)NTOK * H_];    // n1 compact, then n2 compact (fp16)
__device__ __half g_attnH[(size_t)NTOK * H_];   // attn_out compact (fp16)
__device__ __half g_PtH [(size_t)H_ * H_];      // Pt[m][k] = (Wv@Wo)[k][m] (fp16)
__device__ __half g_gateH[(size_t)NTOK * DFF_]; // gate proj (fp16)
__device__ __half g_hbuf [(size_t)NTOK * DFF_]; // h = silu(g)*u (fp16)
__device__ __half g_woT [(size_t)H_ * H_];      // Wo^T (fp16)
__device__ __half g_wvH [(size_t)H_ * H_];      // Wv (fp16)
__device__ __half g_wgT [(size_t)H_ * DFF_];    // w_gate^T [DFF,H] (fp16)
__device__ __half g_wuT [(size_t)H_ * DFF_];    // w_up^T   [DFF,H] (fp16)
__device__ __half g_wdT [(size_t)H_ * DFF_];    // w_down^T [H,DFF] (fp16)

// ---------------- helpers ----------------
__device__ __forceinline__ uint32_t smem_u32(const void* p) {
    uint32_t a;
    asm("{ .reg .u64 t; cvta.to.shared.u64 t, %1; cvt.u32.u64 %0, t; }" : "=r"(a) : "l"(p));
    return a;
}

__device__ __forceinline__ void cp16(uint32_t dst, const void* src) {
    asm volatile("cp.async.cg.shared.global [%0], [%1], 16;" :: "r"(dst), "l"(src));
}

__device__ __forceinline__ void ldsm4(uint32_t* r, uint32_t addr) {
    asm volatile("ldmatrix.sync.aligned.m8n8.x4.shared.b16 {%0,%1,%2,%3}, [%4];"
        : "=r"(r[0]), "=r"(r[1]), "=r"(r[2]), "=r"(r[3]) : "r"(addr));
}

__device__ __forceinline__ void mma_f16(float* d, const uint32_t* a, const uint32_t* b) {
    asm volatile(
        "mma.sync.aligned.m16n8k16.row.col.f32.f16.f16.f32 "
        "{%0,%1,%2,%3}, {%4,%5,%6,%7}, {%8,%9}, {%0,%1,%2,%3};"
        : "+f"(d[0]), "+f"(d[1]), "+f"(d[2]), "+f"(d[3])
        : "r"(a[0]), "r"(a[1]), "r"(a[2]), "r"(a[3]), "r"(b[0]), "r"(b[1]));
}

// ---------------- small kernels ----------------

__global__ void reset_kernel() { g_count = 0; }

__global__ void router_kernel(const float* __restrict__ x,
                              const float* __restrict__ wr,
                              const float* __restrict__ br) {
    int t = blockIdx.x;
    const float4* x4 = (const float4*)(x + (size_t)t * H_);
    const float4* w4 = (const float4*)wr;
    float dot = 0.f, ss = 0.f;
    for (int i = threadIdx.x; i < H_/4; i += blockDim.x) {
        float4 xv = x4[i], wv = w4[i];
        dot += xv.x*wv.x + xv.y*wv.y + xv.z*wv.z + xv.w*wv.w;
        ss  += xv.x*xv.x + xv.y*xv.y + xv.z*xv.z + xv.w*xv.w;
    }
    __shared__ float sd[256], sq[256];
    sd[threadIdx.x] = dot; sq[threadIdx.x] = ss;
    __syncthreads();
    for (int s = 128; s > 0; s >>= 1) {
        if (threadIdx.x < s) { sd[threadIdx.x] += sd[threadIdx.x+s]; sq[threadIdx.x] += sq[threadIdx.x+s]; }
        __syncthreads();
    }
    if (threadIdx.x == 0) {
        float l = sd[0] + br[0];
        g_weights[t] = 1.f / (1.f + expf(-l));
        g_rstd1[t]   = rsqrtf(sq[0] / (float)H_ + EPSF);
    }
}

__global__ void thresh_kernel() {
    __shared__ float s[S_];
    int b = blockIdx.x;
    for (int i = threadIdx.x; i < S_; i += blockDim.x) s[i] = g_weights[(size_t)b * S_ + i];
    __syncthreads();
    for (int k = 2; k <= S_; k <<= 1) {
        for (int j = k >> 1; j > 0; j >>= 1) {
            for (int i = threadIdx.x; i < S_; i += blockDim.x) {
                int ixj = i ^ j;
                if (ixj > i) {
                    float a = s[i], c = s[ixj];
                    bool desc = ((i & k) == 0);
                    if (desc ? (a < c) : (a > c)) { s[i] = c; s[ixj] = a; }
                }
            }
            __syncthreads();
        }
    }
    if (threadIdx.x == 0) g_thresh[b] = s[KCAP - 1];
}

__global__ void select_kernel() {
    int t = blockIdx.x * blockDim.x + threadIdx.x;
    if (t >= NTOK) return;
    if (g_weights[t] >= g_thresh[t / S_]) {
        int p = atomicAdd(&g_count, 1);
        g_selidx[p] = t;
    }
}

__global__ void copyx_kernel(const float* __restrict__ x, float* __restrict__ out) {
    int t = blockIdx.x;
    if (g_weights[t] >= g_thresh[t / S_]) return;
    const float4* x4 = (const float4*)(x + (size_t)t * H_);
    float4* o4 = (float4*)(out + (size_t)t * H_);
    for (int i = threadIdx.x; i < H_/4; i += blockDim.x) o4[i] = x4[i];
}

// n1 = fp16(rmsnorm(x)*norm1_w), compact
__global__ void gather_kernel(const float* __restrict__ x, const float* __restrict__ n1w) {
    int r = blockIdx.x;
    if (r >= g_count) return;
    int t = g_selidx[r];
    float rs = g_rstd1[t];
    const float4* x4 = (const float4*)(x + (size_t)t * H_);
    const float4* w4 = (const float4*)n1w;
    __half2* o2 = (__half2*)(g_bufA + (size_t)r * H_);
    for (int i = threadIdx.x; i < H_/4; i += blockDim.x) {
        float4 xv = x4[i], wv = w4[i];
        o2[2*i]   = __floats2half2_rn(xv.x*rs*wv.x, xv.y*rs*wv.y);
        o2[2*i+1] = __floats2half2_rn(xv.z*rs*wv.z, xv.w*rs*wv.w);
    }
}

// res = x + attn; out[token]=res; bufA = fp16(rmsnorm(res)*norm2_w)
__global__ void res_kernel(const float* __restrict__ x, const float* __restrict__ n2w,
                           float* __restrict__ out) {
    int r = blockIdx.x;
    if (r >= g_count) return;
    int t = g_selidx[r];
    __shared__ float sres[H_];
    __shared__ float red[256];
    const float4* x4 = (const float4*)(x + (size_t)t * H_);
    const __half2* a2 = (const __half2*)(g_attnH + (size_t)r * H_);
    float ss = 0.f;
    for (int i = threadIdx.x; i < H_/4; i += blockDim.x) {
        float4 xv = x4[i];
        float2 av0 = __half22float2(a2[2*i]);
        float2 av1 = __half22float2(a2[2*i+1]);
        float4 rv = make_float4(xv.x+av0.x, xv.y+av0.y, xv.z+av1.x, xv.w+av1.y);
        ((float4*)sres)[i] = rv;
        ss += rv.x*rv.x + rv.y*rv.y + rv.z*rv.z + rv.w*rv.w;
    }
    red[threadIdx.x] = ss;
    __syncthreads();
    for (int s = 128; s > 0; s >>= 1) {
        if (threadIdx.x < s) red[threadIdx.x] += red[threadIdx.x+s];
        __syncthreads();
    }
    float rstd = rsqrtf(red[0] / (float)H_ + EPSF);
    float4* o4 = (float4*)(out + (size_t)t * H_);
    __half2* n2b = (__half2*)(g_bufA + (size_t)r * H_);
    const float4* w4 = (const float4*)n2w;
    for (int i = threadIdx.x; i < H_/4; i += blockDim.x) {
        float4 rv = ((float4*)sres)[i];
        float4 wv = w4[i];
        o4[i] = rv;
        n2b[2*i]   = __floats2half2_rn(rv.x*rstd*wv.x, rv.y*rstd*wv.y);
        n2b[2*i+1] = __floats2half2_rn(rv.z*rstd*wv.z, rv.w*rstd*wv.w);
    }
}

// tiled transpose fp32 -> fp16: dst[c][r] = half(src[r][c])
__global__ void transposeH_kernel(const float* __restrict__ src, __half* __restrict__ dst,
                                  int R, int C) {
    __shared__ float tile[32][33];
    int c0 = blockIdx.x * 32, r0 = blockIdx.y * 32;
    int tx = threadIdx.x, ty = threadIdx.y;
    #pragma unroll
    for (int j = 0; j < 4; j++) {
        int r = r0 + ty + j*8;
        tile[ty + j*8][tx] = src[(size_t)r * C + c0 + tx];
    }
    __syncthreads();
    #pragma unroll
    for (int j = 0; j < 4; j++) {
        int c = c0 + ty + j*8;
        dst[(size_t)c * R + r0 + tx] = __float2half_rn(tile[tx][ty + j*8]);
    }
}

// fp32 -> fp16 copy
__global__ void h_copy_kernel(const float* __restrict__ src, __half* __restrict__ dst, size_t n4) {
    size_t i = (size_t)blockIdx.x * blockDim.x + threadIdx.x;
    if (i >= n4) return;
    float4 v = ((const float4*)src)[i];
    ((__half2*)dst)[2*i]   = __floats2half2_rn(v.x, v.y);
    ((__half2*)dst)[2*i+1] = __floats2half2_rn(v.z, v.w);
}

// ---------------- fp16 mma.sync GEMM ----------------
// C[M,N] = A[M,K] * B[N,K]^T  (half operands, K-major rows, fp32 accumulate).
// CTA 128x256, 8 warps (warp tile 64x64), K_TILE=64 halves (128B rows),
// 4-stage cp.async pipeline, ldmatrix.x4 loads, double-buffered fragments.
// epi: 0 = store fp32, 1 = store fp16, 2 = scatter-add fp32 out[g_selidx[row]*H_+col]
//      3 = fused swiglu: C = fp16(silu(g_gateH[row, col]) * acc)   (requires N == DFF_)
#define STAGES   4
#define KTH      64                 // halves per K-tile
#define RS       72                 // padded row stride in halves (64+8 -> 144B rows)
#define A_ST     (128 * RS)         // halves per A stage
#define B_ST     (256 * RS)         // halves per B stage
#define GSMEM_BYTES ((A_ST + B_ST) * 2 * STAGES)   // 221184

__global__ __launch_bounds__(256, 1) void gemm_h(
    const __half* __restrict__ A, const __half* __restrict__ B, void* __restrict__ Cv,
    int M, int N, int K, int useCount, int epi, float* __restrict__ outp)
{
    int effM = useCount ? g_count : M;
    int rowBase = blockIdx.y * 128;
    if (rowBase >= effM) return;
    int colBase = blockIdx.x * 256;

    extern __shared__ __half smem[];
    uint32_t asBase = smem_u32(smem);
    uint32_t bsBase = asBase + (uint32_t)STAGES * A_ST * 2;

    int tid  = threadIdx.x;
    int wid  = tid >> 5;
    int lane = tid & 31;
    int grp  = lane >> 2;       // 0..7
    int tig  = lane & 3;        // 0..3
    int wm   = (wid & 1) * 64;  // warp row offset (0/64)
    int wn   = (wid >> 1) * 64; // warp col offset (0/64/128/192)

    const __half* Ag = A + (size_t)rowBase * K;
    const __half* Bg = B + (size_t)colBase * K;
    int KT = K >> 6;            // K / 64

    auto load_tile = [&](int s, int kt) {
        int kb = kt << 6;
        uint32_t as = asBase + (uint32_t)s * A_ST * 2;
        uint32_t bs = bsBase + (uint32_t)s * B_ST * 2;
        #pragma unroll
        for (int i = 0; i < 4; i++) {          // A: 1024 16B-chunks
            int c = tid + (i << 8);
            int row = c >> 3, ch = c & 7;
            cp16(as + (uint32_t)(row * RS + ch * 8) * 2,
                 Ag + (size_t)row * K + kb + ch * 8);
        }
        #pragma unroll
        for (int i = 0; i < 8; i++) {          // B: 2048 16B-chunks
            int c = tid + (i << 8);
            int row = c >> 3, ch = c & 7;
            cp16(bs + (uint32_t)(row * RS + ch * 8) * 2,
                 Bg + (size_t)row * K + kb + ch * 8);
        }
        asm volatile("cp.async.commit_group;" ::: "memory");
    };

    #pragma unroll
    for (int p = 0; p < STAGES - 1; p++) load_tile(p, p);

    float acc[4][8][4];
    #pragma unroll
    for (int i = 0; i < 4; i++)
        #pragma unroll
        for (int j = 0; j < 8; j++)
            #pragma unroll
            for (int q = 0; q < 4; q++) acc[i][j][q] = 0.f;

    // per-lane ldmatrix byte offsets (within a stage)
    int lr = lane & 7;
    uint32_t aOff = (uint32_t)((wm + lr + ((lane >> 3) & 1) * 8) * RS + (lane >> 4) * 8) * 2;
    uint32_t bOff = (uint32_t)((wn + lr + (lane >> 4) * 8) * RS + ((lane >> 3) & 1) * 8) * 2;

    uint32_t afr[2][4][4], bfr[2][8][2];

    for (int kt = 0; kt < KT; kt++) {
        int s = kt & (STAGES - 1);
        int remain = KT - 1 - kt;
        if (remain >= 2)      asm volatile("cp.async.wait_group 2;" ::: "memory");
        else if (remain == 1) asm volatile("cp.async.wait_group 1;" ::: "memory");
        else                  asm volatile("cp.async.wait_group 0;" ::: "memory");
        __syncthreads();

        uint32_t aSt = asBase + (uint32_t)s * A_ST * 2;
        uint32_t bSt = bsBase + (uint32_t)s * B_ST * 2;

        // prime fragments for kstep 0 of this tile
        #pragma unroll
        for (int i = 0; i < 4; i++)
            ldsm4(afr[0][i], aSt + aOff + (uint32_t)i * (16 * RS * 2));
        #pragma unroll
        for (int j = 0; j < 4; j++) {
            uint32_t t4[4];
            ldsm4(t4, bSt + bOff + (uint32_t)j * (16 * RS * 2));
            bfr[0][2*j][0] = t4[0]; bfr[0][2*j][1] = t4[1];
            bfr[0][2*j+1][0] = t4[2]; bfr[0][2*j+1][1] = t4[3];
        }

        // issue next tile's global loads while fragments are in flight
        int nt = kt + STAGES - 1;
        if (nt < KT) load_tile(nt & (STAGES - 1), nt);

        #pragma unroll
        for (int ks = 0; ks < 4; ks++) {       // 4 x k16 per K-tile
            int cur = ks & 1, nxt = cur ^ 1;
            if (ks < 3) {
                #pragma unroll
                for (int i = 0; i < 4; i++)
                    ldsm4(afr[nxt][i], aSt + aOff + (uint32_t)i * (16 * RS * 2) + (ks + 1) * 32);
                #pragma unroll
                for (int j = 0; j < 4; j++) {
                    uint32_t t4[4];
                    ldsm4(t4, bSt + bOff + (uint32_t)j * (16 * RS * 2) + (ks + 1) * 32);
                    bfr[nxt][2*j][0] = t4[0]; bfr[nxt][2*j][1] = t4[1];
                    bfr[nxt][2*j+1][0] = t4[2]; bfr[nxt][2*j+1][1] = t4[3];
                }
            }
            #pragma unroll
            for (int i = 0; i < 4; i++)
                #pragma unroll
                for (int j = 0; j < 8; j++)
                    mma_f16(acc[i][j], afr[cur][i], bfr[cur][j]);
        }
    }

    // Epilogue: acc[i][j]: rows (wm+16i+grp, +8), cols wn + 8j + 2*tig (+1)
    #pragma unroll
    for (int i = 0; i < 4; i++) {
        int r0 = rowBase + wm + i * 16 + grp;
        int r1 = r0 + 8;
        #pragma unroll
        for (int j = 0; j < 8; j++) {
            int col = colBase + wn + j * 8 + tig * 2;
            if (epi == 2) {
                if (r0 < effM) {
                    float* op = outp + (size_t)g_selidx[r0] * H_ + col;
                    op[0] += acc[i][j][0]; op[1] += acc[i][j][1];
                }
                if (r1 < effM) {
                    float* op = outp + (size_t)g_selidx[r1] * H_ + col;
                    op[0] += acc[i][j][2]; op[1] += acc[i][j][3];
                }
            } else if (epi == 3) {
                __half* Ch = (__half*)Cv;
                if (r0 < effM) {
                    float2 g = __half22float2(*(const __half2*)(g_gateH + (size_t)r0 * DFF_ + col));
                    float hx = g.x / (1.f + expf(-g.x)) * acc[i][j][0];
                    float hy = g.y / (1.f + expf(-g.y)) * acc[i][j][1];
                    *(__half2*)(Ch + (size_t)r0 * N + col) = __floats2half2_rn(hx, hy);
                }
                if (r1 < effM) {
                    float2 g = __half22float2(*(const __half2*)(g_gateH + (size_t)r1 * DFF_ + col));
                    float hx = g.x / (1.f + expf(-g.x)) * acc[i][j][2];
                    float hy = g.y / (1.f + expf(-g.y)) * acc[i][j][3];
                    *(__half2*)(Ch + (size_t)r1 * N + col) = __floats2half2_rn(hx, hy);
                }
            } else if (epi == 1) {
                __half* Ch = (__half*)Cv;
                if (r0 < effM)
                    *(__half2*)(Ch + (size_t)r0 * N + col) = __floats2half2_rn(acc[i][j][0], acc[i][j][1]);
                if (r1 < effM)
                    *(__half2*)(Ch + (size_t)r1 * N + col) = __floats2half2_rn(acc[i][j][2], acc[i][j][3]);
            } else {
                float* Cf = (float*)Cv;
                if (r0 < effM)
                    *(float2*)(Cf + (size_t)r0 * N + col) = make_float2(acc[i][j][0], acc[i][j][1]);
                if (r1 < effM)
                    *(float2*)(Cf + (size_t)r1 * N + col) = make_float2(acc[i][j][2], acc[i][j][3]);
            }
        }
    }
}

// ---------------- launch ----------------
extern "C" void kernel_launch(void* const* d_in, const int* in_sizes, int n_in,
                              void* d_out, int out_size) {
    const float* x   = (const float*)d_in[0];
    const float* wr  = (const float*)d_in[1];
    const float* br  = (const float*)d_in[2];
    // d_in[3]=Wq, d_in[4]=Wk: unused (softmax over singleton axis == 1 -> ctx = v)
    const float* Wv  = (const float*)d_in[5];
    const float* Wo  = (const float*)d_in[6];
    const float* wg  = (const float*)d_in[7];
    const float* wu  = (const float*)d_in[8];
    const float* wd  = (const float*)d_in[9];
    const float* n1w = (const float*)d_in[10];
    const float* n2w = (const float*)d_in[11];
    float* out = (float*)d_out;

    cudaFuncSetAttribute(gemm_h, cudaFuncAttributeMaxDynamicSharedMemorySize, GSMEM_BYTES);

    __half *p_bufA, *p_attnH, *p_PtH, *p_gateH, *p_hbuf, *p_woT, *p_wvH, *p_wgT, *p_wuT, *p_wdT;
    cudaGetSymbolAddress((void**)&p_bufA,  g_bufA);
    cudaGetSymbolAddress((void**)&p_attnH, g_attnH);
    cudaGetSymbolAddress((void**)&p_PtH,   g_PtH);
    cudaGetSymbolAddress((void**)&p_gateH, g_gateH);
    cudaGetSymbolAddress((void**)&p_hbuf,  g_hbuf);
    cudaGetSymbolAddress((void**)&p_woT,   g_woT);
    cudaGetSymbolAddress((void**)&p_wvH,   g_wvH);
    cudaGetSymbolAddress((void**)&p_wgT,   g_wgT);
    cudaGetSymbolAddress((void**)&p_wuT,   g_wuT);
    cudaGetSymbolAddress((void**)&p_wdT,   g_wdT);

    reset_kernel<<<1, 1>>>();
    router_kernel<<<NTOK, 256>>>(x, wr, br);
    thresh_kernel<<<B_, 1024>>>();
    select_kernel<<<NTOK/256, 256>>>();
    copyx_kernel<<<NTOK, 256>>>(x, out);
    gather_kernel<<<NTOK, 256>>>(x, n1w);

    // weight prep (fp16, K-major B operands)
    dim3 tb(32, 8);
    transposeH_kernel<<<dim3(H_/32,   H_/32),  tb>>>(Wo, p_woT, H_, H_);     // WoT [H,H]
    transposeH_kernel<<<dim3(DFF_/32, H_/32),  tb>>>(wg, p_wgT, H_, DFF_);   // wgT [DFF,H]
    transposeH_kernel<<<dim3(DFF_/32, H_/32),  tb>>>(wu, p_wuT, H_, DFF_);   // wuT [DFF,H]
    transposeH_kernel<<<dim3(H_/32,   DFF_/32),tb>>>(wd, p_wdT, DFF_, H_);   // wdT [H,DFF]
    h_copy_kernel<<<(H_*H_/4)/256, 256>>>(Wv, p_wvH, (size_t)H_*H_/4);

    // Pt = WoT x WvH^T : Pt[m][n] = (Wv@Wo)[n][m], fp16 store
    gemm_h<<<dim3(H_/256, H_/128), 256, GSMEM_BYTES>>>(p_woT, p_wvH, p_PtH, H_, H_, H_, 0, 1, nullptr);
    // attn = n1c x Pt^T (fp16 out)
    gemm_h<<<dim3(H_/256, NTOK/128), 256, GSMEM_BYTES>>>(p_bufA, p_PtH, p_attnH, NTOK, H_, H_, 1, 1, nullptr);
    // res + rmsnorm2
    res_kernel<<<NTOK, 256>>>(x, n2w, out);
    // gate projection (fp16 out)
    gemm_h<<<dim3(DFF_/256, NTOK/128), 256, GSMEM_BYTES>>>(p_bufA, p_wgT, p_gateH, NTOK, DFF_, H_, 1, 1, nullptr);
    // up projection fused with swiglu: h = fp16(silu(gate) * up)
    gemm_h<<<dim3(DFF_/256, NTOK/128), 256, GSMEM_BYTES>>>(p_bufA, p_wuT, p_hbuf,  NTOK, DFF_, H_, 1, 3, nullptr);
    // out[selected] += h x wdT^T
    gemm_h<<<dim3(H_/256, NTOK/128), 256, GSMEM_BYTES>>>(p_hbuf, p_wdT, nullptr, NTOK, H_, DFF_, 1, 2, out);
}

// round 6
// speedup vs baseline: 1.0634x; 1.0634x over previous
#include <cuda_runtime.h>
#include <cuda_fp16.h>
#include <cstdint>
#include <math.h>

// Problem constants
#define B_    4
#define S_    4096
#define H_    2048
#define DFF_  8192
#define NTOK  (B_*S_)      // 16384 tokens
#define KCAP  (S_/2)       // top-k k = 2048
#define EPSF  1e-5f

// ---------------- static device scratch (allocation-free rule) ----------------
__device__ float  g_weights[NTOK];
__device__ float  g_rstd1[NTOK];
__device__ float  g_thresh[B_];
__device__ int    g_selidx[NTOK];
__device__ int    g_count;

__device__ __half g_bufA[(size_t)NTOK * H_];    // n1 compact, then n2 compact (fp16)
__device__ __half g_attnH[(size_t)NTOK * H_];   // attn_out compact (fp16)
__device__ __half g_PtH [(size_t)H_ * H_];      // Pt[m][k] = (Wv@Wo)[k][m] (fp16)
__device__ __half g_hbuf [(size_t)NTOK * DFF_]; // h = silu(g)*u (fp16)
__device__ __half g_woT [(size_t)H_ * H_];      // Wo^T (fp16)
__device__ __half g_wvH [(size_t)H_ * H_];      // Wv (fp16)
__device__ __half g_wguT[(size_t)2 * DFF_ * H_];// interleaved: row 2f = wgT[f], 2f+1 = wuT[f]
__device__ __half g_wdT [(size_t)H_ * DFF_];    // w_down^T [H,DFF] (fp16)

// ---------------- helpers ----------------
__device__ __forceinline__ uint32_t smem_u32(const void* p) {
    uint32_t a;
    asm("{ .reg .u64 t; cvta.to.shared.u64 t, %1; cvt.u32.u64 %0, t; }" : "=r"(a) : "l"(p));
    return a;
}

__device__ __forceinline__ void cp16(uint32_t dst, const void* src) {
    asm volatile("cp.async.cg.shared.global [%0], [%1], 16;" :: "r"(dst), "l"(src));
}

__device__ __forceinline__ void ldsm4(uint32_t* r, uint32_t addr) {
    asm volatile("ldmatrix.sync.aligned.m8n8.x4.shared.b16 {%0,%1,%2,%3}, [%4];"
        : "=r"(r[0]), "=r"(r[1]), "=r"(r[2]), "=r"(r[3]) : "r"(addr));
}

__device__ __forceinline__ void mma_f16(float* d, const uint32_t* a, const uint32_t* b) {
    asm volatile(
        "mma.sync.aligned.m16n8k16.row.col.f32.f16.f16.f32 "
        "{%0,%1,%2,%3}, {%4,%5,%6,%7}, {%8,%9}, {%0,%1,%2,%3};"
        : "+f"(d[0]), "+f"(d[1]), "+f"(d[2]), "+f"(d[3])
        : "r"(a[0]), "r"(a[1]), "r"(a[2]), "r"(a[3]), "r"(b[0]), "r"(b[1]));
}

// ---------------- small kernels ----------------

__global__ void reset_kernel() { g_count = 0; }

__global__ void router_kernel(const float* __restrict__ x,
                              const float* __restrict__ wr,
                              const float* __restrict__ br) {
    int t = blockIdx.x;
    const float4* x4 = (const float4*)(x + (size_t)t * H_);
    const float4* w4 = (const float4*)wr;
    float dot = 0.f, ss = 0.f;
    for (int i = threadIdx.x; i < H_/4; i += blockDim.x) {
        float4 xv = x4[i], wv = w4[i];
        dot += xv.x*wv.x + xv.y*wv.y + xv.z*wv.z + xv.w*wv.w;
        ss  += xv.x*xv.x + xv.y*xv.y + xv.z*xv.z + xv.w*xv.w;
    }
    __shared__ float sd[256], sq[256];
    sd[threadIdx.x] = dot; sq[threadIdx.x] = ss;
    __syncthreads();
    for (int s = 128; s > 0; s >>= 1) {
        if (threadIdx.x < s) { sd[threadIdx.x] += sd[threadIdx.x+s]; sq[threadIdx.x] += sq[threadIdx.x+s]; }
        __syncthreads();
    }
    if (threadIdx.x == 0) {
        float l = sd[0] + br[0];
        g_weights[t] = 1.f / (1.f + expf(-l));
        g_rstd1[t]   = rsqrtf(sq[0] / (float)H_ + EPSF);
    }
}

__global__ void thresh_kernel() {
    __shared__ float s[S_];
    int b = blockIdx.x;
    for (int i = threadIdx.x; i < S_; i += blockDim.x) s[i] = g_weights[(size_t)b * S_ + i];
    __syncthreads();
    for (int k = 2; k <= S_; k <<= 1) {
        for (int j = k >> 1; j > 0; j >>= 1) {
            for (int i = threadIdx.x; i < S_; i += blockDim.x) {
                int ixj = i ^ j;
                if (ixj > i) {
                    float a = s[i], c = s[ixj];
                    bool desc = ((i & k) == 0);
                    if (desc ? (a < c) : (a > c)) { s[i] = c; s[ixj] = a; }
                }
            }
            __syncthreads();
        }
    }
    if (threadIdx.x == 0) g_thresh[b] = s[KCAP - 1];
}

// select list build + out=x for unselected, one block per token
__global__ void selcopy_kernel(const float* __restrict__ x, float* __restrict__ out) {
    int t = blockIdx.x;
    bool sel = g_weights[t] >= g_thresh[t / S_];
    if (sel) {
        if (threadIdx.x == 0) {
            int p = atomicAdd(&g_count, 1);
            g_selidx[p] = t;
        }
        return;
    }
    const float4* x4 = (const float4*)(x + (size_t)t * H_);
    float4* o4 = (float4*)(out + (size_t)t * H_);
    for (int i = threadIdx.x; i < H_/4; i += blockDim.x) o4[i] = x4[i];
}

// n1 = fp16(rmsnorm(x)*norm1_w), compact
__global__ void gather_kernel(const float* __restrict__ x, const float* __restrict__ n1w) {
    int r = blockIdx.x;
    if (r >= g_count) return;
    int t = g_selidx[r];
    float rs = g_rstd1[t];
    const float4* x4 = (const float4*)(x + (size_t)t * H_);
    const float4* w4 = (const float4*)n1w;
    __half2* o2 = (__half2*)(g_bufA + (size_t)r * H_);
    for (int i = threadIdx.x; i < H_/4; i += blockDim.x) {
        float4 xv = x4[i], wv = w4[i];
        o2[2*i]   = __floats2half2_rn(xv.x*rs*wv.x, xv.y*rs*wv.y);
        o2[2*i+1] = __floats2half2_rn(xv.z*rs*wv.z, xv.w*rs*wv.w);
    }
}

// res = x + attn; out[token]=res; bufA = fp16(rmsnorm(res)*norm2_w)
__global__ void res_kernel(const float* __restrict__ x, const float* __restrict__ n2w,
                           float* __restrict__ out) {
    int r = blockIdx.x;
    if (r >= g_count) return;
    int t = g_selidx[r];
    __shared__ float sres[H_];
    __shared__ float red[256];
    const float4* x4 = (const float4*)(x + (size_t)t * H_);
    const __half2* a2 = (const __half2*)(g_attnH + (size_t)r * H_);
    float ss = 0.f;
    for (int i = threadIdx.x; i < H_/4; i += blockDim.x) {
        float4 xv = x4[i];
        float2 av0 = __half22float2(a2[2*i]);
        float2 av1 = __half22float2(a2[2*i+1]);
        float4 rv = make_float4(xv.x+av0.x, xv.y+av0.y, xv.z+av1.x, xv.w+av1.y);
        ((float4*)sres)[i] = rv;
        ss += rv.x*rv.x + rv.y*rv.y + rv.z*rv.z + rv.w*rv.w;
    }
    red[threadIdx.x] = ss;
    __syncthreads();
    for (int s = 128; s > 0; s >>= 1) {
        if (threadIdx.x < s) red[threadIdx.x] += red[threadIdx.x+s];
        __syncthreads();
    }
    float rstd = rsqrtf(red[0] / (float)H_ + EPSF);
    float4* o4 = (float4*)(out + (size_t)t * H_);
    __half2* n2b = (__half2*)(g_bufA + (size_t)r * H_);
    const float4* w4 = (const float4*)n2w;
    for (int i = threadIdx.x; i < H_/4; i += blockDim.x) {
        float4 rv = ((float4*)sres)[i];
        float4 wv = w4[i];
        o4[i] = rv;
        n2b[2*i]   = __floats2half2_rn(rv.x*rstd*wv.x, rv.y*rstd*wv.y);
        n2b[2*i+1] = __floats2half2_rn(rv.z*rstd*wv.z, rv.w*rstd*wv.w);
    }
}

// tiled transpose fp32 -> fp16: dst[(c*mul+off)][r] = half(src[r][c])
__global__ void transposeH_kernel(const float* __restrict__ src, __half* __restrict__ dst,
                                  int R, int C, int mul, int off) {
    __shared__ float tile[32][33];
    int c0 = blockIdx.x * 32, r0 = blockIdx.y * 32;
    int tx = threadIdx.x, ty = threadIdx.y;
    #pragma unroll
    for (int j = 0; j < 4; j++) {
        int r = r0 + ty + j*8;
        tile[ty + j*8][tx] = src[(size_t)r * C + c0 + tx];
    }
    __syncthreads();
    #pragma unroll
    for (int j = 0; j < 4; j++) {
        int c = c0 + ty + j*8;
        dst[(size_t)(c * mul + off) * R + r0 + tx] = __float2half_rn(tile[tx][ty + j*8]);
    }
}

// fp32 -> fp16 copy
__global__ void h_copy_kernel(const float* __restrict__ src, __half* __restrict__ dst, size_t n4) {
    size_t i = (size_t)blockIdx.x * blockDim.x + threadIdx.x;
    if (i >= n4) return;
    float4 v = ((const float4*)src)[i];
    ((__half2*)dst)[2*i]   = __floats2half2_rn(v.x, v.y);
    ((__half2*)dst)[2*i+1] = __floats2half2_rn(v.z, v.w);
}

// ---------------- fp16 mma.sync GEMM ----------------
// C[M,N] = A[M,K] * B[N,K]^T  (half operands, K-major rows, fp32 accumulate).
// CTA 128x256, 8 warps (warp tile 64x64), K_TILE=64 halves, 4-stage cp.async.
// epi: 0 = store fp32, 1 = store fp16, 2 = scatter-add fp32 out[g_selidx[row]*H_+col]
//      4 = gate/up interleaved swiglu: cols pair (gate,up); h[row][col>>1]=fp16(silu(g)*u)
#define STAGES   4
#define KTH      64                 // halves per K-tile
#define RS       72                 // padded row stride in halves (64+8 -> 144B rows)
#define A_ST     (128 * RS)         // halves per A stage
#define B_ST     (256 * RS)         // halves per B stage
#define GSMEM_BYTES ((A_ST + B_ST) * 2 * STAGES)   // 221184

__global__ __launch_bounds__(256, 1) void gemm_h(
    const __half* __restrict__ A, const __half* __restrict__ B, void* __restrict__ Cv,
    int M, int N, int K, int useCount, int epi, float* __restrict__ outp)
{
    int effM = useCount ? g_count : M;
    int rowBase = blockIdx.y * 128;
    if (rowBase >= effM) return;
    int colBase = blockIdx.x * 256;

    extern __shared__ __half smem[];
    uint32_t asBase = smem_u32(smem);
    uint32_t bsBase = asBase + (uint32_t)STAGES * A_ST * 2;

    int tid  = threadIdx.x;
    int wid  = tid >> 5;
    int lane = tid & 31;
    int grp  = lane >> 2;       // 0..7
    int tig  = lane & 3;        // 0..3
    int wm   = (wid & 1) * 64;  // warp row offset (0/64)
    int wn   = (wid >> 1) * 64; // warp col offset (0/64/128/192)

    const __half* Ag = A + (size_t)rowBase * K;
    const __half* Bg = B + (size_t)colBase * K;
    int KT = K >> 6;            // K / 64

    auto load_tile = [&](int s, int kt) {
        int kb = kt << 6;
        uint32_t as = asBase + (uint32_t)s * A_ST * 2;
        uint32_t bs = bsBase + (uint32_t)s * B_ST * 2;
        #pragma unroll
        for (int i = 0; i < 4; i++) {          // A: 1024 16B-chunks
            int c = tid + (i << 8);
            int row = c >> 3, ch = c & 7;
            cp16(as + (uint32_t)(row * RS + ch * 8) * 2,
                 Ag + (size_t)row * K + kb + ch * 8);
        }
        #pragma unroll
        for (int i = 0; i < 8; i++) {          // B: 2048 16B-chunks
            int c = tid + (i << 8);
            int row = c >> 3, ch = c & 7;
            cp16(bs + (uint32_t)(row * RS + ch * 8) * 2,
                 Bg + (size_t)row * K + kb + ch * 8);
        }
        asm volatile("cp.async.commit_group;" ::: "memory");
    };

    #pragma unroll
    for (int p = 0; p < STAGES - 1; p++) load_tile(p, p);

    float acc[4][8][4];
    #pragma unroll
    for (int i = 0; i < 4; i++)
        #pragma unroll
        for (int j = 0; j < 8; j++)
            #pragma unroll
            for (int q = 0; q < 4; q++) acc[i][j][q] = 0.f;

    // per-lane ldmatrix byte offsets (within a stage)
    int lr = lane & 7;
    uint32_t aOff = (uint32_t)((wm + lr + ((lane >> 3) & 1) * 8) * RS + (lane >> 4) * 8) * 2;
    uint32_t bOff = (uint32_t)((wn + lr + (lane >> 4) * 8) * RS + ((lane >> 3) & 1) * 8) * 2;

    for (int kt = 0; kt < KT; kt++) {
        int s = kt & (STAGES - 1);
        int remain = KT - 1 - kt;
        if (remain >= 2)      asm volatile("cp.async.wait_group 2;" ::: "memory");
        else if (remain == 1) asm volatile("cp.async.wait_group 1;" ::: "memory");
        else                  asm volatile("cp.async.wait_group 0;" ::: "memory");
        __syncthreads();

        int nt = kt + STAGES - 1;
        if (nt < KT) load_tile(nt & (STAGES - 1), nt);

        uint32_t aSt = asBase + (uint32_t)s * A_ST * 2;
        uint32_t bSt = bsBase + (uint32_t)s * B_ST * 2;

        #pragma unroll
        for (int ks = 0; ks < 4; ks++) {       // 4 x k16 per K-tile
            uint32_t afr[4][4], bfr[8][2];
            #pragma unroll
            for (int i = 0; i < 4; i++)
                ldsm4(afr[i], aSt + aOff + (uint32_t)i * (16 * RS * 2) + ks * 32);
            #pragma unroll
            for (int j = 0; j < 4; j++) {
                uint32_t t4[4];
                ldsm4(t4, bSt + bOff + (uint32_t)j * (16 * RS * 2) + ks * 32);
                bfr[2*j][0] = t4[0]; bfr[2*j][1] = t4[1];
                bfr[2*j+1][0] = t4[2]; bfr[2*j+1][1] = t4[3];
            }
            #pragma unroll
            for (int i = 0; i < 4; i++)
                #pragma unroll
                for (int j = 0; j < 8; j++)
                    mma_f16(acc[i][j], afr[i], bfr[j]);
        }
    }

    // Epilogue: acc[i][j]: rows (wm+16i+grp, +8), cols wn + 8j + 2*tig (+1)
    #pragma unroll
    for (int i = 0; i < 4; i++) {
        int r0 = rowBase + wm + i * 16 + grp;
        int r1 = r0 + 8;
        #pragma unroll
        for (int j = 0; j < 8; j++) {
            int col = colBase + wn + j * 8 + tig * 2;
            if (epi == 2) {
                if (r0 < effM) {
                    float* op = outp + (size_t)g_selidx[r0] * H_ + col;
                    op[0] += acc[i][j][0]; op[1] += acc[i][j][1];
                }
                if (r1 < effM) {
                    float* op = outp + (size_t)g_selidx[r1] * H_ + col;
                    op[0] += acc[i][j][2]; op[1] += acc[i][j][3];
                }
            } else if (epi == 4) {
                int f = col >> 1;  // even col = gate feature f, odd = up feature f
                if (r0 < effM) {
                    float g = acc[i][j][0], u = acc[i][j][1];
                    g_hbuf[(size_t)r0 * DFF_ + f] = __float2half_rn(g / (1.f + expf(-g)) * u);
                }
                if (r1 < effM) {
                    float g = acc[i][j][2], u = acc[i][j][3];
                    g_hbuf[(size_t)r1 * DFF_ + f] = __float2half_rn(g / (1.f + expf(-g)) * u);
                }
            } else if (epi == 1) {
                __half* Ch = (__half*)Cv;
                if (r0 < effM)
                    *(__half2*)(Ch + (size_t)r0 * N + col) = __floats2half2_rn(acc[i][j][0], acc[i][j][1]);
                if (r1 < effM)
                    *(__half2*)(Ch + (size_t)r1 * N + col) = __floats2half2_rn(acc[i][j][2], acc[i][j][3]);
            } else {
                float* Cf = (float*)Cv;
                if (r0 < effM)
                    *(float2*)(Cf + (size_t)r0 * N + col) = make_float2(acc[i][j][0], acc[i][j][1]);
                if (r1 < effM)
                    *(float2*)(Cf + (size_t)r1 * N + col) = make_float2(acc[i][j][2], acc[i][j][3]);
            }
        }
    }
}

// ---------------- launch ----------------
extern "C" void kernel_launch(void* const* d_in, const int* in_sizes, int n_in,
                              void* d_out, int out_size) {
    const float* x   = (const float*)d_in[0];
    const float* wr  = (const float*)d_in[1];
    const float* br  = (const float*)d_in[2];
    // d_in[3]=Wq, d_in[4]=Wk: unused (softmax over singleton axis == 1 -> ctx = v)
    const float* Wv  = (const float*)d_in[5];
    const float* Wo  = (const float*)d_in[6];
    const float* wg  = (const float*)d_in[7];
    const float* wu  = (const float*)d_in[8];
    const float* wd  = (const float*)d_in[9];
    const float* n1w = (const float*)d_in[10];
    const float* n2w = (const float*)d_in[11];
    float* out = (float*)d_out;

    cudaFuncSetAttribute(gemm_h, cudaFuncAttributeMaxDynamicSharedMemorySize, GSMEM_BYTES);

    __half *p_bufA, *p_attnH, *p_PtH, *p_hbuf, *p_woT, *p_wvH, *p_wguT, *p_wdT;
    cudaGetSymbolAddress((void**)&p_bufA,  g_bufA);
    cudaGetSymbolAddress((void**)&p_attnH, g_attnH);
    cudaGetSymbolAddress((void**)&p_PtH,   g_PtH);
    cudaGetSymbolAddress((void**)&p_hbuf,  g_hbuf);
    cudaGetSymbolAddress((void**)&p_woT,   g_woT);
    cudaGetSymbolAddress((void**)&p_wvH,   g_wvH);
    cudaGetSymbolAddress((void**)&p_wguT,  g_wguT);
    cudaGetSymbolAddress((void**)&p_wdT,   g_wdT);

    reset_kernel<<<1, 1>>>();
    router_kernel<<<NTOK, 256>>>(x, wr, br);
    thresh_kernel<<<B_, 1024>>>();
    selcopy_kernel<<<NTOK, 256>>>(x, out);
    gather_kernel<<<NTOK, 256>>>(x, n1w);

    // weight prep (fp16, K-major B operands)
    dim3 tb(32, 8);
    transposeH_kernel<<<dim3(H_/32,   H_/32),  tb>>>(Wo, p_woT,  H_, H_,   1, 0);  // WoT [H,H]
    transposeH_kernel<<<dim3(DFF_/32, H_/32),  tb>>>(wg, p_wguT, H_, DFF_, 2, 0);  // interleave even
    transposeH_kernel<<<dim3(DFF_/32, H_/32),  tb>>>(wu, p_wguT, H_, DFF_, 2, 1);  // interleave odd
    transposeH_kernel<<<dim3(H_/32,   DFF_/32),tb>>>(wd, p_wdT,  DFF_, H_, 1, 0);  // wdT [H,DFF]
    h_copy_kernel<<<(H_*H_/4)/256, 256>>>(Wv, p_wvH, (size_t)H_*H_/4);

    // Pt = WoT x WvH^T : Pt[m][n] = (Wv@Wo)[n][m], fp16 store
    gemm_h<<<dim3(H_/256, H_/128), 256, GSMEM_BYTES>>>(p_woT, p_wvH, p_PtH, H_, H_, H_, 0, 1, nullptr);
    // attn = n1c x Pt^T (fp16 out)
    gemm_h<<<dim3(H_/256, NTOK/128), 256, GSMEM_BYTES>>>(p_bufA, p_PtH, p_attnH, NTOK, H_, H_, 1, 1, nullptr);
    // res + rmsnorm2
    res_kernel<<<NTOK, 256>>>(x, n2w, out);
    // fused gate+up GEMM with swiglu epilogue: h = fp16(silu(gate)*up)
    gemm_h<<<dim3(2*DFF_/256, NTOK/128), 256, GSMEM_BYTES>>>(p_bufA, p_wguT, nullptr, NTOK, 2*DFF_, H_, 1, 4, nullptr);
    // out[selected] += h x wdT^T
    gemm_h<<<dim3(H_/256, NTOK/128), 256, GSMEM_BYTES>>>(p_hbuf, p_wdT, nullptr, NTOK, H_, DFF_, 1, 2, out);
}